// round 2
// baseline (speedup 1.0000x reference)
#include <cuda_runtime.h>
#include <math.h>

// Problem shapes (fixed by the reference):
//   pred:               [N, 6]      (x1,y1,x2,y2, conf, cls)
//   dropout_preds:      [K, M, 6]
//   dropout_cls_confs:  [K, M, C]   softmax rows (strictly positive)
//   out:                [N]
#define N_PRED 1000
#define M_BOX  2000
#define K_PASS 10
#define C_CLS  80
#define IOU_T  0.5f
#define EPS_F  1e-7f

// One block per pred n; one warp per dropout pass k.
// Each warp scans boxes m in order, 64 at a time, and stops at the first
// chunk containing a hit (exact first-match / "break" semantics).
// Then the warp computes the entropy of the matched class row cooperatively.
__global__ __launch_bounds__(K_PASS * 32, 4)
void ue_cls_kernel(const float* __restrict__ pred,
                   const float* __restrict__ dp,
                   const float* __restrict__ conf,
                   float* __restrict__ out)
{
    const int n    = blockIdx.x;
    const int k    = threadIdx.x >> 5;   // warp id == pass id
    const int lane = threadIdx.x & 31;

    __shared__ float s_u[K_PASS];
    __shared__ int   s_m[K_PASS];

    // Broadcast-load pred box n (L1 broadcast, 4 scalar LDGs).
    const float px1 = pred[n * 6 + 0];
    const float py1 = pred[n * 6 + 1];
    const float px2 = pred[n * 6 + 2];
    const float py2 = pred[n * 6 + 3];
    const float area1 = (px2 - px1) * (py2 - py1);

    const float* __restrict__ dpk = dp + (size_t)k * M_BOX * 6;

    int m_match = -1;

    // 64 boxes per iteration: lane handles m0 = base+lane and m1 = base+lane+32.
    for (int base = 0; base < M_BOX; base += 64) {
        bool hit0 = false, hit1 = false;

        {
            const int m0 = base + lane;          // always < M_BOX (base <= 1984)
            const float* b = dpk + m0 * 6;
            const float2 v01 = *reinterpret_cast<const float2*>(b);      // 8B aligned
            const float2 v23 = *reinterpret_cast<const float2*>(b + 2);
            const float ix1 = fmaxf(px1, v01.x), iy1 = fmaxf(py1, v01.y);
            const float ix2 = fminf(px2, v23.x), iy2 = fminf(py2, v23.y);
            const float inter = fmaxf(ix2 - ix1, 0.0f) * fmaxf(iy2 - iy1, 0.0f);
            const float area2 = (v23.x - v01.x) * (v23.y - v01.y);
            const float iou = inter / (area1 + area2 - inter + EPS_F);
            hit0 = iou > IOU_T;
        }
        {
            const int m1 = base + lane + 32;
            if (m1 < M_BOX) {                    // tail: 2000 % 64 == 16
                const float* b = dpk + m1 * 6;
                const float2 v01 = *reinterpret_cast<const float2*>(b);
                const float2 v23 = *reinterpret_cast<const float2*>(b + 2);
                const float ix1 = fmaxf(px1, v01.x), iy1 = fmaxf(py1, v01.y);
                const float ix2 = fminf(px2, v23.x), iy2 = fminf(py2, v23.y);
                const float inter = fmaxf(ix2 - ix1, 0.0f) * fmaxf(iy2 - iy1, 0.0f);
                const float area2 = (v23.x - v01.x) * (v23.y - v01.y);
                const float iou = inter / (area1 + area2 - inter + EPS_F);
                hit1 = iou > IOU_T;
            }
        }

        const unsigned bal0 = __ballot_sync(0xffffffffu, hit0);
        const unsigned bal1 = __ballot_sync(0xffffffffu, hit1);
        if (bal0) { m_match = base + (__ffs(bal0) - 1); break; }
        if (bal1) { m_match = base + 32 + (__ffs(bal1) - 1); break; }
    }

    if (lane == 0) s_m[k] = m_match;

    if (m_match >= 0) {
        // Cooperative entropy of the matched class row: C=80 = 32+32+16.
        const float* __restrict__ row =
            conf + ((size_t)k * M_BOX + (size_t)m_match) * C_CLS;
        float s = 0.0f;
        {
            float p = row[lane];        s += p * __logf(p);
        }
        {
            float p = row[lane + 32];   s += p * __logf(p);
        }
        if (lane < C_CLS - 64) {
            float p = row[lane + 64];   s += p * __logf(p);
        }
        #pragma unroll
        for (int off = 16; off; off >>= 1)
            s += __shfl_xor_sync(0xffffffffu, s, off);
        // entropy = -s ;  u = 1 - entropy/log(C) = 1 + s/log(C)
        if (lane == 0) s_u[k] = 1.0f + s * (1.0f / logf((float)C_CLS));
    }

    __syncthreads();

    if (threadIdx.x == 0) {
        float sum = 0.0f;
        int   cnt = 0;
        #pragma unroll
        for (int kk = 0; kk < K_PASS; kk++) {
            if (s_m[kk] >= 0) { sum += s_u[kk]; cnt++; }
        }
        out[n] = (cnt > 0) ? (sum / (float)cnt) : __int_as_float(0x7fc00000); // NaN
    }
}

extern "C" void kernel_launch(void* const* d_in, const int* in_sizes, int n_in,
                              void* d_out, int out_size)
{
    const float* pred = (const float*)d_in[0];   // [N,6]
    const float* dp   = (const float*)d_in[1];   // [K,M,6]
    const float* conf = (const float*)d_in[2];   // [K,M,C]
    float* out = (float*)d_out;                  // [N]

    ue_cls_kernel<<<N_PRED, K_PASS * 32>>>(pred, dp, conf, out);
}

// round 4
// speedup vs baseline: 1.6133x; 1.6133x over previous
#include <cuda_runtime.h>
#include <math.h>

// Shapes fixed by the reference:
//   pred:              [N, 6]
//   dropout_preds:     [K, M, 6]
//   dropout_cls_confs: [K, M, C]
//   out:               [N]
#define N_PRED 1000
#define M_BOX  2000
#define K_PASS 10
#define C_CLS  80
#define IOU_T  0.5f
#define EPS_F  1e-7f

// First-match condition, division-free:
//   inter/(a1+a2-inter+eps) > T  <=>  inter > T*(a1+a2-inter+eps)
// (denominator is strictly positive: areas > 0, eps > 0)
__device__ __forceinline__ bool iou_hit(const float* __restrict__ b,
                                        float px1, float py1, float px2, float py2,
                                        float area1e)
{
    const float2 v01 = *reinterpret_cast<const float2*>(b);
    const float2 v23 = *reinterpret_cast<const float2*>(b + 2);
    const float ix1 = fmaxf(px1, v01.x), iy1 = fmaxf(py1, v01.y);
    const float ix2 = fminf(px2, v23.x), iy2 = fminf(py2, v23.y);
    const float inter = fmaxf(ix2 - ix1, 0.0f) * fmaxf(iy2 - iy1, 0.0f);
    const float area2 = (v23.x - v01.x) * (v23.y - v01.y);
    return inter > IOU_T * (area1e + area2 - inter);
}

// One block per pred n; one warp per pass k.
// Warp scans 128 boxes/iter (4 per lane, j-major so j*32+lane == m-base),
// combines with a single REDUX.MIN to get the exact FIRST match index.
__global__ __launch_bounds__(K_PASS * 32)
void ue_cls_kernel(const float* __restrict__ pred,
                   const float* __restrict__ dp,
                   const float* __restrict__ conf,
                   float* __restrict__ out)
{
    const int n    = blockIdx.x;
    const int k    = threadIdx.x >> 5;
    const int lane = threadIdx.x & 31;

    __shared__ float s_u[K_PASS];
    __shared__ int   s_m[K_PASS];

    const float px1 = pred[n * 6 + 0];
    const float py1 = pred[n * 6 + 1];
    const float px2 = pred[n * 6 + 2];
    const float py2 = pred[n * 6 + 3];
    const float area1e = (px2 - px1) * (py2 - py1) + EPS_F;

    const float* __restrict__ dpk = dp + (size_t)k * M_BOX * 6;
    // lane's base pointer; advances by 128*6 floats per chunk
    const float* p = dpk + (size_t)lane * 6;

    int m_match = -1;

    // Main loop: 15 chunks of 128 boxes (covers m in [0,1920)), no bounds checks.
    #pragma unroll 1
    for (int base = 0; base < 1920; base += 128, p += 128 * 6) {
        const bool h0 = iou_hit(p,            px1, py1, px2, py2, area1e);
        const bool h1 = iou_hit(p + 32 * 6,   px1, py1, px2, py2, area1e);
        const bool h2 = iou_hit(p + 64 * 6,   px1, py1, px2, py2, area1e);
        const bool h3 = iou_hit(p + 96 * 6,   px1, py1, px2, py2, area1e);

        int loc = 0x7fffffff;             // j-major index: j*32 + lane == m - base
        if (h3) loc = 96 + lane;
        if (h2) loc = 64 + lane;
        if (h1) loc = 32 + lane;
        if (h0) loc = lane;

        const int r = __reduce_min_sync(0xffffffffu, loc);
        if (r != 0x7fffffff) { m_match = base + r; break; }
    }

    // Tail: m in [1920, 2000) = 2 full groups of 32 + 16.
    if (m_match < 0) {
        const bool h0 = iou_hit(p,          px1, py1, px2, py2, area1e);
        const bool h1 = iou_hit(p + 32 * 6, px1, py1, px2, py2, area1e);
        const bool h2 = (lane < 16) &&
                        iou_hit(p + 64 * 6, px1, py1, px2, py2, area1e);

        int loc = 0x7fffffff;
        if (h2) loc = 64 + lane;
        if (h1) loc = 32 + lane;
        if (h0) loc = lane;

        const int r = __reduce_min_sync(0xffffffffu, loc);
        if (r != 0x7fffffff) m_match = 1920 + r;
    }

    if (lane == 0) s_m[k] = m_match;

    if (m_match >= 0) {
        // Cooperative entropy of matched row: C=80 = 32 + 32 + 16.
        const float* __restrict__ row =
            conf + ((size_t)k * M_BOX + (size_t)m_match) * C_CLS;
        float s;
        {
            const float p0 = row[lane];
            const float p1 = row[lane + 32];
            s = p0 * __logf(p0) + p1 * __logf(p1);
        }
        if (lane < C_CLS - 64) {
            const float p2 = row[lane + 64];
            s += p2 * __logf(p2);
        }
        #pragma unroll
        for (int off = 16; off; off >>= 1)
            s += __shfl_xor_sync(0xffffffffu, s, off);
        // u = 1 - entropy/log(C) = 1 + s/log(C)
        if (lane == 0) s_u[k] = 1.0f + s * (1.0f / logf((float)C_CLS));
    }

    __syncthreads();

    if (threadIdx.x == 0) {
        float sum = 0.0f;
        int   cnt = 0;
        #pragma unroll
        for (int kk = 0; kk < K_PASS; kk++) {
            if (s_m[kk] >= 0) { sum += s_u[kk]; cnt++; }
        }
        out[n] = (cnt > 0) ? (sum / (float)cnt) : __int_as_float(0x7fc00000);
    }
}

extern "C" void kernel_launch(void* const* d_in, const int* in_sizes, int n_in,
                              void* d_out, int out_size)
{
    const float* pred = (const float*)d_in[0];
    const float* dp   = (const float*)d_in[1];
    const float* conf = (const float*)d_in[2];
    float* out = (float*)d_out;

    ue_cls_kernel<<<N_PRED, K_PASS * 32>>>(pred, dp, conf, out);
}

// round 5
// speedup vs baseline: 1.6752x; 1.0384x over previous
#include <cuda_runtime.h>
#include <math.h>

// Shapes fixed by the reference:
//   pred:              [N, 6]
//   dropout_preds:     [K, M, 6]
//   dropout_cls_confs: [K, M, C]
//   out:               [N]
#define N_PRED 1000
#define M_BOX  2000
#define K_PASS 10
#define C_CLS  80
#define EPS_F  1e-7f

// Repacked boxes: one aligned float4 (x1,y1,x2,y2) per box -> 1 LDG.128/eval.
__device__ float4 g_box[K_PASS * M_BOX];

__global__ void prep_kernel(const float* __restrict__ dp)
{
    const int i = blockIdx.x * blockDim.x + threadIdx.x;
    if (i < K_PASS * M_BOX) {
        const float* b = dp + (size_t)i * 6;
        g_box[i] = make_float4(b[0], b[1], b[2], b[3]);
    }
}

// IoU > 0.5  <=>  inter/(a1+a2-inter+eps) > 0.5
//            <=>  1.5*inter > 0.5*(a1+eps+a2)  <=>  3*inter > (a1+eps) + a2
// (denominator strictly positive). s1 = area1 + EPS.
__device__ __forceinline__ bool iou_hit(float4 v,
                                        float px1, float py1, float px2, float py2,
                                        float s1)
{
    const float w = fminf(px2, v.z) - fmaxf(px1, v.x);
    const float h = fminf(py2, v.w) - fmaxf(py1, v.y);
    const float inter3 = (3.0f * fmaxf(w, 0.0f)) * fmaxf(h, 0.0f);
    const float area2  = (v.z - v.x) * (v.w - v.y);
    return inter3 > s1 + area2;
}

// One block per pred n (REVERSED: heavy n launched first so the long scans
// start in wave 1 and light blocks backfill); one warp per pass k.
// Warp scans 128 boxes/iter (4/lane, j-major so j*32+lane == m-base) and
// takes REDUX.MIN for the exact FIRST-match index.
__global__ __launch_bounds__(K_PASS * 32)
void ue_cls_kernel(const float* __restrict__ pred,
                   const float* __restrict__ conf,
                   float* __restrict__ out)
{
    const int n    = (N_PRED - 1) - blockIdx.x;   // heavy blocks first
    const int k    = threadIdx.x >> 5;
    const int lane = threadIdx.x & 31;

    __shared__ float s_u[K_PASS];
    __shared__ int   s_m[K_PASS];

    const float px1 = pred[n * 6 + 0];
    const float py1 = pred[n * 6 + 1];
    const float px2 = pred[n * 6 + 2];
    const float py2 = pred[n * 6 + 3];
    const float s1  = (px2 - px1) * (py2 - py1) + EPS_F;

    const float4* __restrict__ bp = g_box + k * M_BOX + lane;

    int m_match = -1;

    // Main loop: 15 chunks of 128 (m in [0,1920)), no bounds checks.
    #pragma unroll 1
    for (int base = 0; base < 1920; base += 128) {
        // Batch the 4 loads first (max MLP), then evaluate.
        const float4 v0 = bp[base];
        const float4 v1 = bp[base + 32];
        const float4 v2 = bp[base + 64];
        const float4 v3 = bp[base + 96];

        int loc = 0x7fffffff;              // j*32+lane == m-base (j-major)
        if (iou_hit(v3, px1, py1, px2, py2, s1)) loc = 96 + lane;
        if (iou_hit(v2, px1, py1, px2, py2, s1)) loc = 64 + lane;
        if (iou_hit(v1, px1, py1, px2, py2, s1)) loc = 32 + lane;
        if (iou_hit(v0, px1, py1, px2, py2, s1)) loc = lane;

        const int r = __reduce_min_sync(0xffffffffu, loc);
        if (r != 0x7fffffff) { m_match = base + r; break; }
    }

    // Tail: m in [1920, 2000) = 32 + 32 + 16.
    if (m_match < 0) {
        const float4 v0 = bp[1920];
        const float4 v1 = bp[1952];

        int loc = 0x7fffffff;
        if (lane < 16) {
            const float4 v2 = bp[1984];
            if (iou_hit(v2, px1, py1, px2, py2, s1)) loc = 64 + lane;
        }
        if (iou_hit(v1, px1, py1, px2, py2, s1)) loc = 32 + lane;
        if (iou_hit(v0, px1, py1, px2, py2, s1)) loc = lane;

        const int r = __reduce_min_sync(0xffffffffu, loc);
        if (r != 0x7fffffff) m_match = 1920 + r;
    }

    if (lane == 0) s_m[k] = m_match;

    if (m_match >= 0) {
        // Cooperative entropy of the matched row: C=80 = 32 + 32 + 16.
        const float* __restrict__ row =
            conf + ((size_t)k * M_BOX + (size_t)m_match) * C_CLS;
        float s;
        {
            const float p0 = row[lane];
            const float p1 = row[lane + 32];
            s = p0 * __logf(p0) + p1 * __logf(p1);
        }
        if (lane < C_CLS - 64) {
            const float p2 = row[lane + 64];
            s += p2 * __logf(p2);
        }
        #pragma unroll
        for (int off = 16; off; off >>= 1)
            s += __shfl_xor_sync(0xffffffffu, s, off);
        // u = 1 - entropy/log(C) = 1 + s/log(C)
        if (lane == 0) s_u[k] = 1.0f + s * (1.0f / logf((float)C_CLS));
    }

    __syncthreads();

    if (threadIdx.x == 0) {
        float sum = 0.0f;
        int   cnt = 0;
        #pragma unroll
        for (int kk = 0; kk < K_PASS; kk++) {
            if (s_m[kk] >= 0) { sum += s_u[kk]; cnt++; }
        }
        out[n] = (cnt > 0) ? (sum / (float)cnt) : __int_as_float(0x7fc00000);
    }
}

extern "C" void kernel_launch(void* const* d_in, const int* in_sizes, int n_in,
                              void* d_out, int out_size)
{
    const float* pred = (const float*)d_in[0];
    const float* dp   = (const float*)d_in[1];
    const float* conf = (const float*)d_in[2];
    float* out = (float*)d_out;

    prep_kernel<<<(K_PASS * M_BOX + 255) / 256, 256>>>(dp);
    ue_cls_kernel<<<N_PRED, K_PASS * 32>>>(pred, conf, out);
}